// round 11
// baseline (speedup 1.0000x reference)
#include <cuda_runtime.h>

// Problem constants
#define TPB    128
#define NSAMP  32000      // B*length = 32*1000
#define LEN    1000
#define TROW   1002
#define DDIM   16
#define EDIM   32
#define HDIM   64

typedef unsigned long long u64;

// Packed fp32x2 FMA (Blackwell sm_10x): d = a*b + c on two packed fp32 lanes.
__device__ __forceinline__ u64 ffma2(u64 a, u64 b, u64 c) {
    u64 d;
    asm("fma.rn.f32x2 %0, %1, %2, %3;" : "=l"(d) : "l"(a), "l"(b), "l"(c));
    return d;
}
__device__ __forceinline__ float hsum2(u64 v) {
    float lo, hi;
    asm("mov.b64 {%0, %1}, %2;" : "=f"(lo), "=f"(hi) : "l"(v));
    return lo + hi;
}
__device__ __forceinline__ u64 pack2(float lo, float hi) {
    u64 v;
    asm("mov.b64 %0, {%1, %2};" : "=l"(v) : "f"(lo), "f"(hi));
    return v;
}
__device__ __forceinline__ void unpack2(u64 v, float& lo, float& hi) {
    asm("mov.b64 {%0, %1}, %2;" : "=f"(lo), "=f"(hi) : "l"(v));
}

// Scratch for per-(d, n) log|dJ| — deterministic reduction in a second kernel.
__device__ float g_dj[DDIM * NSAMP];

// Shared memory layout (float offsets), static (<48KB):
#define OFF_W0E  0        // 64 x 32
#define OFF_W1T  2048     // 64 cols x 72 stride (padded transpose of W1)
#define OFF_W2   6656     // 64 x 64 row-major
#define OFF_W0X  10752    // 64
#define OFF_WO   10816    // 64
#define OFF_B0   10880    // 64
#define OFF_B1   10944    // 64
#define OFF_B2   11008    // 64
#define SMEM_FLOATS 11072 // 44288 bytes -> 3 blocks/SM by smem
#define W1T_STRIDE 72     // 288B per col: 16B-aligned broadcast reads

extern "C" __global__ void __launch_bounds__(TPB, 3)
mlp_fwd_kernel(const float* __restrict__ x,  const float* __restrict__ emb,
               const float* __restrict__ W0, const float* __restrict__ b0,
               const float* __restrict__ W1, const float* __restrict__ b1,
               const float* __restrict__ W2, const float* __restrict__ b2,
               const float* __restrict__ Wo, const float* __restrict__ bo,
               float* __restrict__ out)
{
    __shared__ float smem[SMEM_FLOATS];
    const int tid = threadIdx.x;
    const int d   = blockIdx.y;

    float* sW0e = smem + OFF_W0E;
    float* sW1T = smem + OFF_W1T;
    float* sW2  = smem + OFF_W2;
    float* sW0x = smem + OFF_W0X;
    float* sWo  = smem + OFF_WO;
    float* sB0  = smem + OFF_B0;
    float* sB1  = smem + OFF_B1;
    float* sB2  = smem + OFF_B2;

    // ---- cooperative weight staging ----
    {
        const float* g0 = W0 + d * HDIM * (EDIM + 1);   // 64 x 33
#pragma unroll 1
        for (int idx = tid; idx < HDIM * (EDIM + 1); idx += TPB) {
            int h = idx / 33, e = idx - h * 33;
            float v = g0[idx];
            if (e == 32) sW0x[h] = v; else sW0e[h * EDIM + e] = v;
        }
        const float* g1 = W1 + d * 4096;
#pragma unroll 1
        for (int idx = tid; idx < 4096; idx += TPB) {
            int j = idx >> 6, i = idx & 63;
            sW1T[i * W1T_STRIDE + j] = g1[idx];         // transpose: col i contiguous
        }
        const float4* g2 = (const float4*)(W2 + d * 4096);
        float4* s2 = (float4*)sW2;
#pragma unroll
        for (int k = 0; k < 8; ++k) s2[tid + k * TPB] = g2[tid + k * TPB];
        if (tid < HDIM) {
            sWo[tid] = Wo[d * HDIM + tid];
            sB0[tid] = b0[d * HDIM + tid];
            sB1[tid] = b1[d * HDIM + tid];
            sB2[tid] = b2[d * HDIM + tid];
        }
    }
    __syncthreads();

    const int n   = blockIdx.x * TPB + tid;     // grid.x*TPB == NSAMP exactly
    const int b   = n / LEN;
    const int l   = n - b * LEN;
    const int row = b * TROW + 2 + l;           // LAGS = 2
    const float xt = x[row * DDIM + d];

    u64 acc[32];
    u64 mask0 = 0, mask1 = 0, mask2 = 0;

    // ================= Phase A : activation path =================
    {
        // Pack the 32-wide embedding into 16 f32x2 regs (dies after layer 0).
        u64 epk[16];
        {
            const float4* er = (const float4*)(emb + (size_t)row * EDIM);
#pragma unroll
            for (int k = 0; k < 8; ++k) {
                float4 v = er[k];
                epk[2 * k]     = pack2(v.x, v.y);
                epk[2 * k + 1] = pack2(v.z, v.w);
            }
        }
#pragma unroll
        for (int p = 0; p < 32; ++p) acc[p] = 0;

        // layer0 rows fused with column-accumulate into W1^T
#pragma unroll 1
        for (int i = 0; i < HDIM; i += 2) {
            u64 d0a = 0, d0b = 0, d1a = 0, d1b = 0;
            const ulonglong2* r0 = (const ulonglong2*)(sW0e + i * EDIM);
            const ulonglong2* r1 = r0 + 8;   // next row (32 floats = 8 x 16B)
#pragma unroll
            for (int k = 0; k < 8; ++k) {
                ulonglong2 w0 = r0[k], w1 = r1[k];
                u64 e0 = epk[2 * k], e1 = epk[2 * k + 1];
                d0a = ffma2(w0.x, e0, d0a);
                d1a = ffma2(w1.x, e0, d1a);
                d0b = ffma2(w0.y, e1, d0b);
                d1b = ffma2(w1.y, e1, d1b);
            }
            float z0 = hsum2(d0a) + hsum2(d0b) + sW0x[i + 0] * xt + sB0[i + 0];
            float z1 = hsum2(d1a) + hsum2(d1b) + sW0x[i + 1] * xt + sB0[i + 1];
            float a0 = (z0 >= 0.f) ? z0 : 0.2f * z0;
            float a1 = (z1 >= 0.f) ? z1 : 0.2f * z1;
            mask0 |= (u64)(z0 < 0.f) << i;
            mask0 |= (u64)(z1 < 0.f) << (i + 1);
            u64 av0 = pack2(a0, a0), av1 = pack2(a1, a1);
            const ulonglong2* c0 = (const ulonglong2*)(sW1T + (i + 0) * W1T_STRIDE);
            const ulonglong2* c1 = (const ulonglong2*)(sW1T + (i + 1) * W1T_STRIDE);
#pragma unroll
            for (int k = 0; k < 16; ++k) {
                ulonglong2 w0 = c0[k], w1 = c1[k];
                acc[2 * k]     = ffma2(av0, w0.x, acc[2 * k]);
                acc[2 * k + 1] = ffma2(av0, w0.y, acc[2 * k + 1]);
                acc[2 * k]     = ffma2(av1, w1.x, acc[2 * k]);
                acc[2 * k + 1] = ffma2(av1, w1.y, acc[2 * k + 1]);
            }
        }

        // gate layer 1: a1 = leaky(acc + b1), record mask1
        {
            const u64* bb = (const u64*)sB1;
#pragma unroll
            for (int p = 0; p < 32; ++p) {
                float za, zb, bA, bB;
                unpack2(acc[p], za, zb);
                unpack2(bb[p],  bA, bB);
                za += bA; zb += bB;
                float aa = (za >= 0.f) ? za : 0.2f * za;
                float ab = (zb >= 0.f) ? zb : 0.2f * zb;
                mask1 |= (u64)(za < 0.f) << (2 * p);
                mask1 |= (u64)(zb < 0.f) << (2 * p + 1);
                acc[p] = pack2(aa, ab);
            }
        }

        // layer2 rows fused with output head, record mask2
        float ra0 = 0.f, ra1 = 0.f;
#pragma unroll 1
        for (int j = 0; j < HDIM; j += 2) {
            u64 p0a = 0, p0b = 0, p1a = 0, p1b = 0;
            const ulonglong2* r0 = (const ulonglong2*)(sW2 + j * HDIM);
            const ulonglong2* r1 = r0 + 16;  // next row (64 floats = 16 x 16B)
#pragma unroll
            for (int k = 0; k < 16; ++k) {
                ulonglong2 w0 = r0[k], w1 = r1[k];
                u64 a0 = acc[2 * k], a1 = acc[2 * k + 1];
                p0a = ffma2(w0.x, a0, p0a);
                p1a = ffma2(w1.x, a0, p1a);
                p0b = ffma2(w0.y, a1, p0b);
                p1b = ffma2(w1.y, a1, p1b);
            }
            float za = hsum2(p0a) + hsum2(p0b) + sB2[j + 0];
            float zb = hsum2(p1a) + hsum2(p1b) + sB2[j + 1];
            mask2 |= (u64)(za < 0.f) << j;
            mask2 |= (u64)(zb < 0.f) << (j + 1);
            float a2a = (za >= 0.f) ? za : 0.2f * za;
            float a2b = (zb >= 0.f) ? zb : 0.2f * zb;
            ra0 = fmaf(sWo[j],     a2a, ra0);
            ra1 = fmaf(sWo[j + 1], a2b, ra1);
        }
        out[n * DDIM + d] = ra0 + ra1 + bo[d];
    }

    // ================= Phase T : tangent path =================
    {
#pragma unroll
        for (int p = 0; p < 32; ++p) acc[p] = 0;

        // t0 = gate0 * W0x, column-accumulate through W1^T
#pragma unroll 1
        for (int i = 0; i < HDIM; i += 2) {
            float w0v = sW0x[i], w1v = sW0x[i + 1];
            float t0 = ((mask0 >> i) & 1ull)       ? 0.2f * w0v : w0v;
            float t1 = ((mask0 >> (i + 1)) & 1ull) ? 0.2f * w1v : w1v;
            u64 tv0 = pack2(t0, t0), tv1 = pack2(t1, t1);
            const ulonglong2* c0 = (const ulonglong2*)(sW1T + (i + 0) * W1T_STRIDE);
            const ulonglong2* c1 = (const ulonglong2*)(sW1T + (i + 1) * W1T_STRIDE);
#pragma unroll
            for (int k = 0; k < 16; ++k) {
                ulonglong2 w0 = c0[k], w1 = c1[k];
                acc[2 * k]     = ffma2(tv0, w0.x, acc[2 * k]);
                acc[2 * k + 1] = ffma2(tv0, w0.y, acc[2 * k + 1]);
                acc[2 * k]     = ffma2(tv1, w1.x, acc[2 * k]);
                acc[2 * k + 1] = ffma2(tv1, w1.y, acc[2 * k + 1]);
            }
        }

        // gate layer 1 with recorded mask1
#pragma unroll
        for (int p = 0; p < 32; ++p) {
            float ta, tb;
            unpack2(acc[p], ta, tb);
            ta = ((mask1 >> (2 * p)) & 1ull)     ? 0.2f * ta : ta;
            tb = ((mask1 >> (2 * p + 1)) & 1ull) ? 0.2f * tb : tb;
            acc[p] = pack2(ta, tb);
        }

        // layer2 rows, gate with mask2, fuse with Jacobian head
        float rt0 = 0.f, rt1 = 0.f;
#pragma unroll 1
        for (int j = 0; j < HDIM; j += 2) {
            u64 p0a = 0, p0b = 0, p1a = 0, p1b = 0;
            const ulonglong2* r0 = (const ulonglong2*)(sW2 + j * HDIM);
            const ulonglong2* r1 = r0 + 16;
#pragma unroll
            for (int k = 0; k < 16; ++k) {
                ulonglong2 w0 = r0[k], w1 = r1[k];
                u64 t0 = acc[2 * k], t1 = acc[2 * k + 1];
                p0a = ffma2(w0.x, t0, p0a);
                p1a = ffma2(w1.x, t0, p1a);
                p0b = ffma2(w0.y, t1, p0b);
                p1b = ffma2(w1.y, t1, p1b);
            }
            float ta = hsum2(p0a) + hsum2(p0b);
            float tb = hsum2(p1a) + hsum2(p1b);
            ta = ((mask2 >> j) & 1ull)       ? 0.2f * ta : ta;
            tb = ((mask2 >> (j + 1)) & 1ull) ? 0.2f * tb : tb;
            rt0 = fmaf(sWo[j],     ta, rt0);
            rt1 = fmaf(sWo[j + 1], tb, rt1);
        }
        g_dj[d * NSAMP + n] = logf(fabsf(rt0 + rt1));
    }
}

extern "C" __global__ void __launch_bounds__(256)
reduce_logdet_kernel(float* __restrict__ out)
{
    int n = blockIdx.x * 256 + threadIdx.x;
    if (n < NSAMP) {
        float s = 0.f;
#pragma unroll
        for (int d = 0; d < DDIM; ++d) s += g_dj[d * NSAMP + n];
        out[NSAMP * DDIM + n] = s;   // logdet region after residuals
    }
}

extern "C" void kernel_launch(void* const* d_in, const int* in_sizes, int n_in,
                              void* d_out, int out_size)
{
    const float* x   = (const float*)d_in[0];
    const float* emb = (const float*)d_in[1];
    const float* W0  = (const float*)d_in[2];
    const float* b0  = (const float*)d_in[3];
    const float* W1  = (const float*)d_in[4];
    const float* b1  = (const float*)d_in[5];
    const float* W2  = (const float*)d_in[6];
    const float* b2  = (const float*)d_in[7];
    const float* Wo  = (const float*)d_in[8];
    const float* bo  = (const float*)d_in[9];
    float* out = (float*)d_out;

    dim3 grid(NSAMP / TPB, DDIM);   // (250, 16)
    mlp_fwd_kernel<<<grid, TPB>>>(x, emb, W0, b0, W1, b1, W2, b2, Wo, bo, out);
    reduce_logdet_kernel<<<(NSAMP + 255) / 256, 256>>>(out);
}